// round 2
// baseline (speedup 1.0000x reference)
#include <cuda_runtime.h>
#include <cstdint>
#include <math.h>

#define D_DIM   1024
#define T_DIM   50
#define STRIDEQ 10
#define NUM_POS 16
#define MAX_B   4096
#define MAX_KP  13108   /* ceil(131072/10) */

// ---- device scratch (static; no allocations allowed) ----
__device__ ulonglong2 g_q[MAX_KP];   // packed queue labels (plane0, plane1)
__device__ ulonglong2 g_a[MAX_B];    // packed anchor labels
__device__ float      g_per[MAX_B];  // per-anchor loss
__device__ unsigned   g_counter;

// ------------------------------------------------------------------
// Kernel 1: pack labels for strided queue rows and anchors.
// One warp per row. Also resets the completion counter.
// ------------------------------------------------------------------
__global__ void prep_labels(const int* __restrict__ xlab,
                            const int* __restrict__ qlab,
                            int B, int Kp) {
    if (blockIdx.x == 0 && threadIdx.x == 0) g_counter = 0;
    int warp = (blockIdx.x * blockDim.x + threadIdx.x) >> 5;
    int lane = threadIdx.x & 31;
    if (warp >= Kp + B) return;

    const int* lp;
    if (warp < Kp) lp = qlab + (long long)warp * STRIDEQ * (T_DIM * 2);
    else           lp = xlab + (long long)(warp - Kp) * (T_DIM * 2);

    int2 va = ((const int2*)lp)[lane];            // t = lane
    int l0b = 0, l1b = 0;
    if (32 + lane < T_DIM) {                      // t = 32+lane
        int2 vb = ((const int2*)lp)[32 + lane];
        l0b = vb.x; l1b = vb.y;
    }
    unsigned b0lo = __ballot_sync(0xffffffffu, va.x != 0);
    unsigned b1lo = __ballot_sync(0xffffffffu, va.y != 0);
    unsigned b0hi = __ballot_sync(0xffffffffu, l0b != 0);
    unsigned b1hi = __ballot_sync(0xffffffffu, l1b != 0);
    if (lane == 0) {
        ulonglong2 v;
        v.x = (unsigned long long)b0lo | ((unsigned long long)b0hi << 32);
        v.y = (unsigned long long)b1lo | ((unsigned long long)b1hi << 32);
        if (warp < Kp) g_q[warp]      = v;
        else           g_a[warp - Kp] = v;
    }
}

// ------------------------------------------------------------------
// Kernel 2 (fused): per anchor — scan (warp 0) || stage anchor (warps
// 8-15); then 16 gathered dot products with on-the-fly norms; per-
// anchor loss; last block reduces the deterministic mean.
// ------------------------------------------------------------------
__global__ void __launch_bounds__(512)
loss_fused(const float* __restrict__ xq, const float* __restrict__ qf,
           float* __restrict__ out, int B, int Kp) {
    __shared__ float  s_anchor[D_DIM];     // 4 KB
    __shared__ float  s_ssq[256];          // per-thread partial |q|^2
    __shared__ int    s_sel[NUM_POS];
    __shared__ int    s_cnt;
    __shared__ float  s_loss[NUM_POS];
    __shared__ int    s_last;
    __shared__ double s_red[512];

    int b    = blockIdx.x;
    int tid  = threadIdx.x;
    int w    = tid >> 5;
    int lane = tid & 31;

    // ---- stage anchor row + squared partials (threads 256..511) ----
    if (tid >= 256) {
        int i = tid - 256;                  // 0..255 float4s
        float4 v = ((const float4*)(xq + (long long)b * D_DIM))[i];
        ((float4*)s_anchor)[i] = v;
        s_ssq[i] = v.x * v.x + v.y * v.y + v.z * v.z + v.w * v.w;
    }

    // ---- concurrent scan (warp 0) ----
    if (w == 0) {
        ulonglong2 av = g_a[b];
        unsigned long long a0 = av.x, a1 = av.y;
        unsigned long long da = a0 & a1;   // diag states (1,1)
        unsigned long long xa = a0 ^ a1;   // axis states

        float c  = 1.0f / (sqrtf(2.0f) + 1e-8f);
        float cc = c * c;
        float d2 = cc + cc;

        int total = 0;
        for (int kb = 0; kb < Kp; kb += 32) {
            int k = kb + lane;
            bool pred = false;
            if (k < Kp) {
                ulonglong2 qv = g_q[k];
                unsigned long long q0 = qv.x, q1 = qv.y;
                unsigned long long dq = q0 & q1;
                unsigned long long xk = q0 ^ q1;
                unsigned long long m1  = (xa & xk) & ((a0 & q0) | (a1 & q1));
                unsigned long long mc  = (da & xk) | (xa & dq);
                unsigned long long mdd = da & dq;
                float s = (float)__popcll(m1)
                        + (float)__popcll(mc)  * c
                        + (float)__popcll(mdd) * d2;
                pred = ((s / 50.0f) >= 0.5f);
            }
            unsigned m = __ballot_sync(0xffffffffu, pred);
            if (pred) {
                int rank = total + __popc(m & ((1u << lane) - 1u));
                if (rank < NUM_POS) s_sel[rank] = k;
            }
            total += __popc(m);
            if (total >= NUM_POS) break;
        }
        if (lane == 0) s_cnt = (total < NUM_POS) ? total : NUM_POS;
    }
    __syncthreads();

    // ---- 16 gathered dots with fused k-norm ----
    int cnt = s_cnt;
    float loss = 0.f;
    if (w < cnt) {
        int kp = s_sel[w];
        const float4* pk = (const float4*)(qf + (long long)kp * STRIDEQ * D_DIM);
        const float4* pa = (const float4*)s_anchor;
        float dot = 0.f, kss = 0.f;
#pragma unroll
        for (int i = 0; i < D_DIM / 4 / 32; i++) {
            float4 a  = pa[lane + i * 32];
            float4 kk = pk[lane + i * 32];
            dot += a.x * kk.x + a.y * kk.y + a.z * kk.z + a.w * kk.w;
            kss += kk.x * kk.x + kk.y * kk.y + kk.z * kk.z + kk.w * kk.w;
        }
#pragma unroll
        for (int o = 16; o; o >>= 1) {
            dot += __shfl_xor_sync(0xffffffffu, dot, o);
            kss += __shfl_xor_sync(0xffffffffu, kss, o);
        }
        // anchor |q|^2 from staged partials (deterministic fixed order)
        float qss = s_ssq[lane] + s_ssq[lane + 32] + s_ssq[lane + 64]
                  + s_ssq[lane + 96] + s_ssq[lane + 128] + s_ssq[lane + 160]
                  + s_ssq[lane + 192] + s_ssq[lane + 224];
#pragma unroll
        for (int o = 16; o; o >>= 1) qss += __shfl_xor_sync(0xffffffffu, qss, o);

        float inv_q = 1.0f / (sqrtf(qss) + 1e-8f);
        float inv_k = 1.0f / (sqrtf(kss) + 1e-8f);
        float s = dot * inv_q * inv_k * 2.0f;       // / TEMPERATURE(0.5)
        float z = -s;                                // -log_sigmoid(s)
        loss = fmaxf(z, 0.f) + log1pf(expf(-fabsf(z)));
    }
    if (lane == 0 && w < NUM_POS) s_loss[w] = loss;
    __syncthreads();

    if (tid == 0) {
        float sum = 0.f;
#pragma unroll
        for (int i = 0; i < NUM_POS; i++) sum += s_loss[i];
        g_per[b] = (cnt > 0) ? (sum / (float)cnt) : 0.f;
        __threadfence();
        unsigned t = atomicAdd(&g_counter, 1u);
        s_last = (t == (unsigned)(gridDim.x - 1)) ? 1 : 0;
    }
    __syncthreads();

    // ---- last block: deterministic double-precision mean ----
    if (s_last) {
        double acc = 0.0;
        for (int i = tid; i < B; i += 512) acc += (double)g_per[i];
        s_red[tid] = acc;
        __syncthreads();
        for (int s = 256; s; s >>= 1) {
            if (tid < s) s_red[tid] += s_red[tid + s];
            __syncthreads();
        }
        if (tid == 0) out[0] = (float)(s_red[0] / (double)B);
    }
}

extern "C" void kernel_launch(void* const* d_in, const int* in_sizes, int n_in,
                              void* d_out, int out_size) {
    const float* xq   = (const float*)d_in[0];
    const int*   xlab = (const int*)  d_in[1];
    const float* qf   = (const float*)d_in[2];
    const int*   qlab = (const int*)  d_in[3];

    int B  = in_sizes[0] / D_DIM;                 // 4096
    int K  = in_sizes[2] / D_DIM;                 // 131072
    int Kp = (K + STRIDEQ - 1) / STRIDEQ;         // 13108

    int warps  = Kp + B;
    int blocks = (warps * 32 + 255) / 256;
    prep_labels<<<blocks, 256>>>(xlab, qlab, B, Kp);
    loss_fused <<<B, 512>>>(xq, qf, (float*)d_out, B, Kp);
}

// round 3
// speedup vs baseline: 1.5927x; 1.5927x over previous
#include <cuda_runtime.h>
#include <cstdint>
#include <math.h>

#define D_DIM   1024
#define T_DIM   50
#define STRIDEQ 10
#define NUM_POS 16
#define MAX_B   4096
#define MAX_KP  13108   /* ceil(131072/10) */
#define W_WIN   4096    /* fixed predicate window (128 mask words) */
#define AG      4       /* anchors per mask_eval block */

// ---- device scratch (static; no allocations allowed) ----
__device__ ulonglong2 g_q[MAX_KP];          // packed queue labels
__device__ ulonglong2 g_a[MAX_B];           // packed anchor labels
__device__ uint4      g_mask[MAX_B * 32];   // 128 words / anchor (16B-aligned)
__device__ float      g_per[MAX_B];
__device__ unsigned   g_counter;

// ------------------------------------------------------------------
// Kernel 1: pack labels (strided queue rows + anchors). Warp per row.
// ------------------------------------------------------------------
__global__ void prep_labels(const int* __restrict__ xlab,
                            const int* __restrict__ qlab,
                            int B, int Kp) {
    if (blockIdx.x == 0 && threadIdx.x == 0) g_counter = 0;
    int warp = (blockIdx.x * blockDim.x + threadIdx.x) >> 5;
    int lane = threadIdx.x & 31;
    if (warp >= Kp + B) return;

    const int* lp = (warp < Kp)
        ? qlab + (long long)warp * STRIDEQ * (T_DIM * 2)
        : xlab + (long long)(warp - Kp) * (T_DIM * 2);

    int2 va = ((const int2*)lp)[lane];
    int l0b = 0, l1b = 0;
    if (32 + lane < T_DIM) {
        int2 vb = ((const int2*)lp)[32 + lane];
        l0b = vb.x; l1b = vb.y;
    }
    unsigned b0lo = __ballot_sync(0xffffffffu, va.x != 0);
    unsigned b1lo = __ballot_sync(0xffffffffu, va.y != 0);
    unsigned b0hi = __ballot_sync(0xffffffffu, l0b != 0);
    unsigned b1hi = __ballot_sync(0xffffffffu, l1b != 0);
    if (lane == 0) {
        ulonglong2 v;
        v.x = (unsigned long long)b0lo | ((unsigned long long)b0hi << 32);
        v.y = (unsigned long long)b1lo | ((unsigned long long)b1hi << 32);
        if (warp < Kp) g_q[warp]      = v;
        else           g_a[warp - Kp] = v;
    }
}

// ------------------------------------------------------------------
// Device helper: label-similarity predicate (exact fp32 as reference).
// ------------------------------------------------------------------
__device__ __forceinline__ bool pair_pred(
    unsigned long long a0, unsigned long long a1,
    unsigned long long da, unsigned long long xa,
    unsigned long long q0, unsigned long long q1,
    float c, float d2) {
    unsigned long long dq = q0 & q1;
    unsigned long long xk = q0 ^ q1;
    unsigned long long m1  = (xa & xk) & ~(a0 ^ q0);  // same-axis matches
    unsigned long long mc  = (da & xk) | (xa & dq);
    unsigned long long mdd = da & dq;
    float s = (float)__popcll(m1)
            + (float)__popcll(mc)  * c
            + (float)__popcll(mdd) * d2;
    return s >= 25.0f;   // == (s/50 >= 0.5), exact (25/50=0.5 exact, monotone)
}

// ------------------------------------------------------------------
// Kernel 2: full-window mask eval. Block = 256 thr, AG anchors/block.
// No serial chains: pure throughput. Writes 128-word bitmask/anchor.
// ------------------------------------------------------------------
__global__ void __launch_bounds__(256)
mask_eval(int B, int Kp) {
    __shared__ ulonglong2 s_q[256];
    int tid  = threadIdx.x;
    int lane = tid & 31;
    int w    = tid >> 5;
    int ab   = blockIdx.x * AG;

    unsigned long long a0[AG], a1[AG], da[AG], xa[AG];
#pragma unroll
    for (int a = 0; a < AG; a++) {
        ulonglong2 av = g_a[ab + a];
        a0[a] = av.x; a1[a] = av.y;
        da[a] = av.x & av.y; xa[a] = av.x ^ av.y;
    }
    float c  = 1.0f / (sqrtf(2.0f) + 1e-8f);
    float cc = c * c;
    float d2 = cc + cc;

    unsigned* maskw = (unsigned*)g_mask;
#pragma unroll 1
    for (int chunk = 0; chunk < W_WIN / 256; chunk++) {
        int k = chunk * 256 + tid;
        ulonglong2 qv = make_ulonglong2(0ull, 0ull);
        if (k < Kp) qv = g_q[k];
        s_q[tid] = qv;
        __syncthreads();
        unsigned long long q0 = s_q[tid].x, q1 = s_q[tid].y;
        bool inb = (k < Kp);
#pragma unroll
        for (int a = 0; a < AG; a++) {
            bool pred = inb && pair_pred(a0[a], a1[a], da[a], xa[a], q0, q1, c, d2);
            unsigned m = __ballot_sync(0xffffffffu, pred);
            if (lane == 0)
                maskw[(ab + a) * (W_WIN / 32) + chunk * 8 + w] = m;
        }
        __syncthreads();
    }
}

// ------------------------------------------------------------------
// Kernel 3 (fused): bitmask select + 16 gathered dots (norms fused)
// + per-anchor loss + last-block deterministic mean.
// ------------------------------------------------------------------
__global__ void __launch_bounds__(512)
loss_fused(const float* __restrict__ xq, const float* __restrict__ qf,
           float* __restrict__ out, int B, int Kp) {
    __shared__ float  s_anchor[D_DIM];
    __shared__ float  s_ssq[256];
    __shared__ int    s_sel[NUM_POS];
    __shared__ int    s_cnt;
    __shared__ float  s_loss[NUM_POS];
    __shared__ int    s_last;
    __shared__ double s_red[512];

    int b    = blockIdx.x;
    int tid  = threadIdx.x;
    int w    = tid >> 5;
    int lane = tid & 31;

    // ---- stage anchor row + squared partials (threads 256..511) ----
    if (tid >= 256) {
        int i = tid - 256;
        float4 v = ((const float4*)(xq + (long long)b * D_DIM))[i];
        ((float4*)s_anchor)[i] = v;
        s_ssq[i] = v.x * v.x + v.y * v.y + v.z * v.z + v.w * v.w;
    }

    // ---- warp 0: select first <=16 hits from precomputed bitmask ----
    if (w == 0) {
        uint4 mv = g_mask[b * 32 + lane];     // words 4*lane .. 4*lane+3
        unsigned wd[4] = {mv.x, mv.y, mv.z, mv.w};
        int my = __popc(wd[0]) + __popc(wd[1]) + __popc(wd[2]) + __popc(wd[3]);
        // exclusive prefix sum over lanes
        int pre = my;
#pragma unroll
        for (int o = 1; o < 32; o <<= 1) {
            int v = __shfl_up_sync(0xffffffffu, pre, o);
            if (lane >= o) pre += v;
        }
        int total = __shfl_sync(0xffffffffu, pre, 31);
        pre -= my;                             // exclusive
        // extract set bits in order while rank < 16
        int rank = pre;
        if (pre < NUM_POS && my > 0) {
#pragma unroll
            for (int j = 0; j < 4; j++) {
                unsigned word = wd[j];
                while (word && rank < NUM_POS) {
                    int bit = __ffs(word) - 1;
                    word &= word - 1;
                    s_sel[rank++] = (4 * lane + j) * 32 + bit;
                }
            }
        }
        // ---- rare fallback: fewer than 16 hits in the window ----
        if (total < NUM_POS) {
            ulonglong2 av = g_a[b];
            unsigned long long a0 = av.x, a1 = av.y;
            unsigned long long da = a0 & a1, xa = a0 ^ a1;
            float c  = 1.0f / (sqrtf(2.0f) + 1e-8f);
            float cc = c * c; float d2 = cc + cc;
            for (int kb = W_WIN; kb < Kp; kb += 32) {
                int k = kb + lane;
                bool pred = false;
                if (k < Kp) {
                    ulonglong2 qv = g_q[k];
                    pred = pair_pred(a0, a1, da, xa, qv.x, qv.y, c, d2);
                }
                unsigned m = __ballot_sync(0xffffffffu, pred);
                if (pred) {
                    int r = total + __popc(m & ((1u << lane) - 1u));
                    if (r < NUM_POS) s_sel[r] = k;
                }
                total += __popc(m);
                if (total >= NUM_POS) break;
            }
        }
        if (lane == 0) s_cnt = (total < NUM_POS) ? total : NUM_POS;
    }
    __syncthreads();

    // ---- 16 gathered dots with fused norms ----
    int cnt = s_cnt;
    float loss = 0.f;
    if (w < cnt) {
        int kp = s_sel[w];
        const float4* pk = (const float4*)(qf + (long long)kp * STRIDEQ * D_DIM);
        const float4* pa = (const float4*)s_anchor;
        float dot = 0.f, kss = 0.f;
#pragma unroll
        for (int i = 0; i < D_DIM / 4 / 32; i++) {
            float4 a  = pa[lane + i * 32];
            float4 kk = pk[lane + i * 32];
            dot += a.x * kk.x + a.y * kk.y + a.z * kk.z + a.w * kk.w;
            kss += kk.x * kk.x + kk.y * kk.y + kk.z * kk.z + kk.w * kk.w;
        }
#pragma unroll
        for (int o = 16; o; o >>= 1) {
            dot += __shfl_xor_sync(0xffffffffu, dot, o);
            kss += __shfl_xor_sync(0xffffffffu, kss, o);
        }
        float qss = s_ssq[lane] + s_ssq[lane + 32] + s_ssq[lane + 64]
                  + s_ssq[lane + 96] + s_ssq[lane + 128] + s_ssq[lane + 160]
                  + s_ssq[lane + 192] + s_ssq[lane + 224];
#pragma unroll
        for (int o = 16; o; o >>= 1) qss += __shfl_xor_sync(0xffffffffu, qss, o);

        float inv_q = 1.0f / (sqrtf(qss) + 1e-8f);
        float inv_k = 1.0f / (sqrtf(kss) + 1e-8f);
        float s = dot * inv_q * inv_k * 2.0f;     // / TEMPERATURE(0.5)
        float z = -s;                              // -log_sigmoid(s)
        loss = fmaxf(z, 0.f) + log1pf(expf(-fabsf(z)));
    }
    if (lane == 0 && w < NUM_POS) s_loss[w] = loss;
    __syncthreads();

    if (tid == 0) {
        float sum = 0.f;
#pragma unroll
        for (int i = 0; i < NUM_POS; i++) sum += s_loss[i];
        g_per[b] = (cnt > 0) ? (sum / (float)cnt) : 0.f;
        __threadfence();
        unsigned t = atomicAdd(&g_counter, 1u);
        s_last = (t == (unsigned)(gridDim.x - 1)) ? 1 : 0;
    }
    __syncthreads();

    if (s_last) {
        double acc = 0.0;
        for (int i = tid; i < B; i += 512) acc += (double)g_per[i];
        s_red[tid] = acc;
        __syncthreads();
        for (int s = 256; s; s >>= 1) {
            if (tid < s) s_red[tid] += s_red[tid + s];
            __syncthreads();
        }
        if (tid == 0) out[0] = (float)(s_red[0] / (double)B);
    }
}

extern "C" void kernel_launch(void* const* d_in, const int* in_sizes, int n_in,
                              void* d_out, int out_size) {
    const float* xq   = (const float*)d_in[0];
    const int*   xlab = (const int*)  d_in[1];
    const float* qf   = (const float*)d_in[2];
    const int*   qlab = (const int*)  d_in[3];

    int B  = in_sizes[0] / D_DIM;                 // 4096
    int K  = in_sizes[2] / D_DIM;                 // 131072
    int Kp = (K + STRIDEQ - 1) / STRIDEQ;         // 13108

    int warps  = Kp + B;
    int blocks = (warps * 32 + 255) / 256;
    prep_labels<<<blocks, 256>>>(xlab, qlab, B, Kp);
    mask_eval  <<<B / AG, 256>>>(B, Kp);
    loss_fused <<<B, 512>>>(xq, qf, (float*)d_out, B, Kp);
}

// round 4
// speedup vs baseline: 5.2033x; 3.2671x over previous
#include <cuda_runtime.h>
#include <cstdint>
#include <math.h>

#define D_DIM   1024
#define T_DIM   50
#define STRIDEQ 10
#define NUM_POS 16
#define MAX_B   4096
#define MAX_KP  13108   /* ceil(131072/10) */
#define W_WIN   4096    /* parallel predicate window */
#define AG      4       /* anchors per mask_eval block */

// ---- device scratch (static; no allocations allowed) ----
__device__ ulonglong2 g_q[MAX_KP];          // packed queue labels
__device__ ulonglong2 g_a[MAX_B];           // packed anchor labels
__device__ int        g_sel[MAX_B * NUM_POS];
__device__ int        g_cnt[MAX_B];         // hits found so far (<=16)
__device__ float      g_per[MAX_B];
__device__ unsigned   g_counter;

// ------------------------------------------------------------------
// Kernel 1: pack labels (strided queue rows + anchors). Warp per row.
// ------------------------------------------------------------------
__global__ void prep_labels(const int* __restrict__ xlab,
                            const int* __restrict__ qlab,
                            int B, int Kp) {
    if (blockIdx.x == 0 && threadIdx.x == 0) g_counter = 0;
    int warp = (blockIdx.x * blockDim.x + threadIdx.x) >> 5;
    int lane = threadIdx.x & 31;
    if (warp >= Kp + B) return;

    const int* lp = (warp < Kp)
        ? qlab + (long long)warp * STRIDEQ * (T_DIM * 2)
        : xlab + (long long)(warp - Kp) * (T_DIM * 2);

    int2 va = ((const int2*)lp)[lane];
    int l0b = 0, l1b = 0;
    if (32 + lane < T_DIM) {
        int2 vb = ((const int2*)lp)[32 + lane];
        l0b = vb.x; l1b = vb.y;
    }
    unsigned b0lo = __ballot_sync(0xffffffffu, va.x != 0);
    unsigned b1lo = __ballot_sync(0xffffffffu, va.y != 0);
    unsigned b0hi = __ballot_sync(0xffffffffu, l0b != 0);
    unsigned b1hi = __ballot_sync(0xffffffffu, l1b != 0);
    if (lane == 0) {
        ulonglong2 v;
        v.x = (unsigned long long)b0lo | ((unsigned long long)b0hi << 32);
        v.y = (unsigned long long)b1lo | ((unsigned long long)b1hi << 32);
        if (warp < Kp) g_q[warp]      = v;
        else           g_a[warp - Kp] = v;
    }
}

// ------------------------------------------------------------------
// Predicate (exact fp32 as validated in R1-R3).
// ------------------------------------------------------------------
__device__ __forceinline__ bool pair_pred(
    unsigned long long a0, unsigned long long a1,
    unsigned long long da, unsigned long long xa,
    unsigned long long q0, unsigned long long q1,
    float c, float d2) {
    unsigned long long dq = q0 & q1;
    unsigned long long xk = q0 ^ q1;
    unsigned long long m1  = (xa & xk) & ~(a0 ^ q0);
    unsigned long long mc  = (da & xk) | (xa & dq);
    unsigned long long mdd = da & dq;
    float s = (float)__popcll(m1)
            + (float)__popcll(mc)  * c
            + (float)__popcll(mdd) * d2;
    return s >= 25.0f;
}

// ------------------------------------------------------------------
// Kernel 2: window mask eval + fused ordered selection (<=16).
// Block = 256 thr, AG anchors/block. Masks kept in smem.
// ------------------------------------------------------------------
__global__ void __launch_bounds__(256)
mask_select(int B, int Kp) {
    __shared__ ulonglong2 s_q[256];
    __shared__ unsigned   s_mask[AG][W_WIN / 32];   // 4 x 128 words
    int tid  = threadIdx.x;
    int lane = tid & 31;
    int w    = tid >> 5;
    int ab   = blockIdx.x * AG;

    unsigned long long a0[AG], a1[AG], da[AG], xa[AG];
#pragma unroll
    for (int a = 0; a < AG; a++) {
        ulonglong2 av = g_a[ab + a];
        a0[a] = av.x; a1[a] = av.y;
        da[a] = av.x & av.y; xa[a] = av.x ^ av.y;
    }
    float c  = 1.0f / (sqrtf(2.0f) + 1e-8f);
    float cc = c * c;
    float d2 = cc + cc;

#pragma unroll 1
    for (int chunk = 0; chunk < W_WIN / 256; chunk++) {
        int k = chunk * 256 + tid;               // always < W_WIN <= Kp
        s_q[tid] = g_q[k];
        __syncthreads();
        unsigned long long q0 = s_q[tid].x, q1 = s_q[tid].y;
#pragma unroll
        for (int a = 0; a < AG; a++) {
            bool pred = pair_pred(a0[a], a1[a], da[a], xa[a], q0, q1, c, d2);
            unsigned m = __ballot_sync(0xffffffffu, pred);
            if (lane == 0) s_mask[a][chunk * 8 + w] = m;
        }
        __syncthreads();
    }

    // ---- fused selection: warp a handles anchor ab+a ----
    if (w < AG) {
        int b = ab + w;
        unsigned wd[4];
#pragma unroll
        for (int j = 0; j < 4; j++) wd[j] = s_mask[w][4 * lane + j];
        int my = __popc(wd[0]) + __popc(wd[1]) + __popc(wd[2]) + __popc(wd[3]);
        int pre = my;
#pragma unroll
        for (int o = 1; o < 32; o <<= 1) {
            int v = __shfl_up_sync(0xffffffffu, pre, o);
            if (lane >= o) pre += v;
        }
        int total = __shfl_sync(0xffffffffu, pre, 31);
        pre -= my;                               // exclusive
        int rank = pre;
        if (pre < NUM_POS && my > 0) {
#pragma unroll
            for (int j = 0; j < 4; j++) {
                unsigned word = wd[j];
                while (word && rank < NUM_POS) {
                    int bit = __ffs(word) - 1;
                    word &= word - 1;
                    g_sel[b * NUM_POS + rank++] = (4 * lane + j) * 32 + bit;
                }
            }
        }
        if (lane == 0) g_cnt[b] = (total < NUM_POS) ? total : NUM_POS;
    }
}

// ------------------------------------------------------------------
// Kernel 3: block-parallel ordered completion over [W_WIN, Kp) for
// anchors with < NUM_POS hits in the window. 256 thr / anchor-block.
// ------------------------------------------------------------------
__global__ void __launch_bounds__(256)
tier2(int B, int Kp) {
    int b    = blockIdx.x;
    int tid  = threadIdx.x;
    int lane = tid & 31;
    int w    = tid >> 5;
    __shared__ int      s_total;
    __shared__ int      s_done;
    __shared__ unsigned s_bal[8];

    if (tid == 0) {
        int t = g_cnt[b];
        s_total = t;
        s_done  = (t >= NUM_POS);
    }
    __syncthreads();
    if (s_done) return;

    ulonglong2 av = g_a[b];
    unsigned long long a0 = av.x, a1 = av.y;
    unsigned long long da = a0 & a1, xa = a0 ^ a1;
    float c  = 1.0f / (sqrtf(2.0f) + 1e-8f);
    float cc = c * c;
    float d2 = cc + cc;

    for (int base = W_WIN; base < Kp; base += 256) {
        int k = base + tid;
        bool pred = false;
        if (k < Kp) {
            ulonglong2 qv = g_q[k];
            pred = pair_pred(a0, a1, da, xa, qv.x, qv.y, c, d2);
        }
        unsigned m = __ballot_sync(0xffffffffu, pred);
        if (lane == 0) s_bal[w] = m;
        __syncthreads();
        if (w == 0) {
            unsigned word = (lane < 8) ? s_bal[lane] : 0u;
            int cw = __popc(word);
            int pre = cw;
#pragma unroll
            for (int o = 1; o < 8; o <<= 1) {
                int v = __shfl_up_sync(0xffffffffu, pre, o);
                if (lane >= o) pre += v;
            }
            int tot  = __shfl_sync(0xffffffffu, pre, 7);
            int excl = pre - cw;
            int cur  = s_total;
            int rank = cur + excl;
            while (word && rank < NUM_POS) {
                int bit = __ffs(word) - 1;
                word &= word - 1;
                g_sel[b * NUM_POS + rank++] = base + lane * 32 + bit;
            }
            if (lane == 0) {
                s_total = cur + tot;
                if (s_total >= NUM_POS) s_done = 1;
            }
        }
        __syncthreads();
        if (s_done) break;
    }
    if (tid == 0) g_cnt[b] = (s_total < NUM_POS) ? s_total : NUM_POS;
}

// ------------------------------------------------------------------
// Kernel 4: per anchor, 16 gathered dots (norms fused) + loss +
// last-block deterministic mean. (Validated numeric path.)
// ------------------------------------------------------------------
__global__ void __launch_bounds__(512)
loss_kernel(const float* __restrict__ xq, const float* __restrict__ qf,
            float* __restrict__ out, int B) {
    __shared__ float  s_anchor[D_DIM];
    __shared__ float  s_ssq[256];
    __shared__ float  s_loss[NUM_POS];
    __shared__ int    s_last;
    __shared__ double s_red[512];

    int b    = blockIdx.x;
    int tid  = threadIdx.x;
    int w    = tid >> 5;
    int lane = tid & 31;

    if (tid >= 256) {
        int i = tid - 256;
        float4 v = ((const float4*)(xq + (long long)b * D_DIM))[i];
        ((float4*)s_anchor)[i] = v;
        s_ssq[i] = v.x * v.x + v.y * v.y + v.z * v.z + v.w * v.w;
    }
    __syncthreads();

    int cnt = g_cnt[b];
    float loss = 0.f;
    if (w < cnt) {
        int kp = g_sel[b * NUM_POS + w];
        const float4* pk = (const float4*)(qf + (long long)kp * STRIDEQ * D_DIM);
        const float4* pa = (const float4*)s_anchor;
        float dot = 0.f, kss = 0.f;
#pragma unroll
        for (int i = 0; i < D_DIM / 4 / 32; i++) {
            float4 a  = pa[lane + i * 32];
            float4 kk = pk[lane + i * 32];
            dot += a.x * kk.x + a.y * kk.y + a.z * kk.z + a.w * kk.w;
            kss += kk.x * kk.x + kk.y * kk.y + kk.z * kk.z + kk.w * kk.w;
        }
#pragma unroll
        for (int o = 16; o; o >>= 1) {
            dot += __shfl_xor_sync(0xffffffffu, dot, o);
            kss += __shfl_xor_sync(0xffffffffu, kss, o);
        }
        float qss = s_ssq[lane] + s_ssq[lane + 32] + s_ssq[lane + 64]
                  + s_ssq[lane + 96] + s_ssq[lane + 128] + s_ssq[lane + 160]
                  + s_ssq[lane + 192] + s_ssq[lane + 224];
#pragma unroll
        for (int o = 16; o; o >>= 1) qss += __shfl_xor_sync(0xffffffffu, qss, o);

        float inv_q = 1.0f / (sqrtf(qss) + 1e-8f);
        float inv_k = 1.0f / (sqrtf(kss) + 1e-8f);
        float s = dot * inv_q * inv_k * 2.0f;     // / TEMPERATURE(0.5)
        float z = -s;                              // -log_sigmoid(s)
        loss = fmaxf(z, 0.f) + log1pf(expf(-fabsf(z)));
    }
    if (lane == 0 && w < NUM_POS) s_loss[w] = loss;
    __syncthreads();

    if (tid == 0) {
        float sum = 0.f;
#pragma unroll
        for (int i = 0; i < NUM_POS; i++) sum += (i < cnt) ? s_loss[i] : 0.f;
        g_per[b] = (cnt > 0) ? (sum / (float)cnt) : 0.f;
        __threadfence();
        unsigned t = atomicAdd(&g_counter, 1u);
        s_last = (t == (unsigned)(gridDim.x - 1)) ? 1 : 0;
    }
    __syncthreads();

    if (s_last) {
        double acc = 0.0;
        for (int i = tid; i < B; i += 512) acc += (double)g_per[i];
        s_red[tid] = acc;
        __syncthreads();
        for (int s = 256; s; s >>= 1) {
            if (tid < s) s_red[tid] += s_red[tid + s];
            __syncthreads();
        }
        if (tid == 0) out[0] = (float)(s_red[0] / (double)B);
    }
}

extern "C" void kernel_launch(void* const* d_in, const int* in_sizes, int n_in,
                              void* d_out, int out_size) {
    const float* xq   = (const float*)d_in[0];
    const int*   xlab = (const int*)  d_in[1];
    const float* qf   = (const float*)d_in[2];
    const int*   qlab = (const int*)  d_in[3];

    int B  = in_sizes[0] / D_DIM;                 // 4096
    int K  = in_sizes[2] / D_DIM;                 // 131072
    int Kp = (K + STRIDEQ - 1) / STRIDEQ;         // 13108

    int warps  = Kp + B;
    int blocks = (warps * 32 + 255) / 256;
    prep_labels<<<blocks, 256>>>(xlab, qlab, B, Kp);
    mask_select<<<B / AG, 256>>>(B, Kp);
    tier2      <<<B, 256>>>(B, Kp);
    loss_kernel<<<B, 512>>>(xq, qf, (float*)d_out, B);
}

// round 5
// speedup vs baseline: 5.7845x; 1.1117x over previous
#include <cuda_runtime.h>
#include <cstdint>
#include <math.h>

#define D_DIM   1024
#define T_DIM   50
#define STRIDEQ 10
#define NUM_POS 16
#define MAX_B   4096
#define MAX_KP  13108   /* ceil(131072/10) */
#define CHUNK   2048    /* adaptive eval granularity */

// ---- device scratch (static; no allocations allowed) ----
__device__ ulonglong2 g_q[MAX_KP];          // packed queue labels
__device__ ulonglong2 g_a[MAX_B];           // packed anchor labels
__device__ int        g_sel[MAX_B * NUM_POS];
__device__ int        g_cnt[MAX_B];
__device__ float      g_per[MAX_B];
__device__ unsigned   g_counter;

// ------------------------------------------------------------------
// Kernel 1: pack labels (strided queue rows + anchors). Warp per row.
// ------------------------------------------------------------------
__global__ void prep_labels(const int* __restrict__ xlab,
                            const int* __restrict__ qlab,
                            int B, int Kp) {
    if (blockIdx.x == 0 && threadIdx.x == 0) g_counter = 0;
    int warp = (blockIdx.x * blockDim.x + threadIdx.x) >> 5;
    int lane = threadIdx.x & 31;
    if (warp >= Kp + B) return;

    const int* lp = (warp < Kp)
        ? qlab + (long long)warp * STRIDEQ * (T_DIM * 2)
        : xlab + (long long)(warp - Kp) * (T_DIM * 2);

    int2 va = ((const int2*)lp)[lane];
    int l0b = 0, l1b = 0;
    if (32 + lane < T_DIM) {
        int2 vb = ((const int2*)lp)[32 + lane];
        l0b = vb.x; l1b = vb.y;
    }
    unsigned b0lo = __ballot_sync(0xffffffffu, va.x != 0);
    unsigned b1lo = __ballot_sync(0xffffffffu, va.y != 0);
    unsigned b0hi = __ballot_sync(0xffffffffu, l0b != 0);
    unsigned b1hi = __ballot_sync(0xffffffffu, l1b != 0);
    if (lane == 0) {
        ulonglong2 v;
        v.x = (unsigned long long)b0lo | ((unsigned long long)b0hi << 32);
        v.y = (unsigned long long)b1lo | ((unsigned long long)b1hi << 32);
        if (warp < Kp) g_q[warp]      = v;
        else           g_a[warp - Kp] = v;
    }
}

// ------------------------------------------------------------------
// Predicate (exact fp32 as validated in R1-R4).
// ------------------------------------------------------------------
__device__ __forceinline__ bool pair_pred(
    unsigned long long a0, unsigned long long a1,
    unsigned long long da, unsigned long long xa,
    unsigned long long q0, unsigned long long q1,
    float c, float d2) {
    unsigned long long dq = q0 & q1;
    unsigned long long xk = q0 ^ q1;
    unsigned long long m1  = (xa & xk) & ~(a0 ^ q0);
    unsigned long long mc  = (da & xk) | (xa & dq);
    unsigned long long mdd = da & dq;
    float s = (float)__popcll(m1)
            + (float)__popcll(mc)  * c
            + (float)__popcll(mdd) * d2;
    return s >= 25.0f;
}

// ------------------------------------------------------------------
// Kernel 2: adaptive parallel selection. Block (256 thr) per anchor.
// Chunks of 2048 preds, per-warp ballot words to smem (no per-iter
// block sync), per-chunk early-exit count, final ordered extraction.
// ------------------------------------------------------------------
__global__ void __launch_bounds__(256)
select_kernel(int B, int Kp) {
    __shared__ unsigned s_words[448];    // ceil(13108/32)=410 used (+pad)
    __shared__ int      s_total;
    int b    = blockIdx.x;
    int tid  = threadIdx.x;
    int lane = tid & 31;
    int w    = tid >> 5;

    ulonglong2 av = g_a[b];
    unsigned long long a0 = av.x, a1 = av.y;
    unsigned long long da = a0 & a1, xa = a0 ^ a1;
    float c  = 1.0f / (sqrtf(2.0f) + 1e-8f);
    float cc = c * c;
    float d2 = cc + cc;

    if (tid == 0) s_total = 0;

    int total     = 0;
    int chunk_end = 0;
#pragma unroll 1
    for (int base = 0; base < Kp; base += CHUNK) {
        int lim   = (base + CHUNK < Kp) ? base + CHUNK : Kp;
        int nIter = (lim - base + 255) >> 8;
#pragma unroll 1
        for (int i = 0; i < nIter; i++) {
            int k = base + i * 256 + tid;
            bool pred = false;
            if (k < lim) {
                ulonglong2 qv = g_q[k];
                pred = pair_pred(a0, a1, da, xa, qv.x, qv.y, c, d2);
            }
            unsigned m = __ballot_sync(0xffffffffu, pred);
            if (lane == 0) s_words[(base >> 5) + i * 8 + w] = m;
        }
        __syncthreads();
        // count this chunk's words (warp 0)
        if (w == 0) {
            int w0 = base >> 5;
            int nw = nIter * 8;
            int cw = __popc(s_words[w0 + lane]);
            if (nw > 32) cw += __popc(s_words[w0 + 32 + lane]);
#pragma unroll
            for (int o = 16; o; o >>= 1) cw += __shfl_xor_sync(0xffffffffu, cw, o);
            if (lane == 0) s_total += cw;
        }
        __syncthreads();
        total     = s_total;
        chunk_end = lim;
        if (total >= NUM_POS) break;
    }

    // ---- ordered extraction of first <=16 hits (warp 0) ----
    if (w == 0) {
        int nwords = (chunk_end + 31) >> 5;
        int run = 0;
        for (int g = 0; g * 32 < nwords && run < NUM_POS; g++) {
            int wi = g * 32 + lane;
            unsigned word = (wi < nwords) ? s_words[wi] : 0u;
            int my = __popc(word);
            int pre = my;
#pragma unroll
            for (int o = 1; o < 32; o <<= 1) {
                int v = __shfl_up_sync(0xffffffffu, pre, o);
                if (lane >= o) pre += v;
            }
            int gtot = __shfl_sync(0xffffffffu, pre, 31);
            int rank = run + pre - my;           // exclusive prefix
            while (word && rank < NUM_POS) {
                int bit = __ffs(word) - 1;
                word &= word - 1;
                g_sel[b * NUM_POS + rank++] = wi * 32 + bit;
            }
            run += gtot;
        }
        if (lane == 0) g_cnt[b] = (total < NUM_POS) ? total : NUM_POS;
    }
}

// ------------------------------------------------------------------
// Kernel 3: per anchor, 16 gathered dots (norms fused) + loss +
// last-block deterministic mean. (Validated numeric path.)
// ------------------------------------------------------------------
__global__ void __launch_bounds__(512)
loss_kernel(const float* __restrict__ xq, const float* __restrict__ qf,
            float* __restrict__ out, int B) {
    __shared__ float  s_anchor[D_DIM];
    __shared__ float  s_ssq[256];
    __shared__ float  s_loss[NUM_POS];
    __shared__ int    s_last;
    __shared__ double s_red[512];

    int b    = blockIdx.x;
    int tid  = threadIdx.x;
    int w    = tid >> 5;
    int lane = tid & 31;

    if (tid >= 256) {
        int i = tid - 256;
        float4 v = ((const float4*)(xq + (long long)b * D_DIM))[i];
        ((float4*)s_anchor)[i] = v;
        s_ssq[i] = v.x * v.x + v.y * v.y + v.z * v.z + v.w * v.w;
    }
    __syncthreads();

    int cnt = g_cnt[b];
    float loss = 0.f;
    if (w < cnt) {
        int kp = g_sel[b * NUM_POS + w];
        const float4* pk = (const float4*)(qf + (long long)kp * STRIDEQ * D_DIM);
        const float4* pa = (const float4*)s_anchor;
        float dot = 0.f, kss = 0.f;
#pragma unroll
        for (int i = 0; i < D_DIM / 4 / 32; i++) {
            float4 a  = pa[lane + i * 32];
            float4 kk = pk[lane + i * 32];
            dot += a.x * kk.x + a.y * kk.y + a.z * kk.z + a.w * kk.w;
            kss += kk.x * kk.x + kk.y * kk.y + kk.z * kk.z + kk.w * kk.w;
        }
#pragma unroll
        for (int o = 16; o; o >>= 1) {
            dot += __shfl_xor_sync(0xffffffffu, dot, o);
            kss += __shfl_xor_sync(0xffffffffu, kss, o);
        }
        float qss = s_ssq[lane] + s_ssq[lane + 32] + s_ssq[lane + 64]
                  + s_ssq[lane + 96] + s_ssq[lane + 128] + s_ssq[lane + 160]
                  + s_ssq[lane + 192] + s_ssq[lane + 224];
#pragma unroll
        for (int o = 16; o; o >>= 1) qss += __shfl_xor_sync(0xffffffffu, qss, o);

        float inv_q = 1.0f / (sqrtf(qss) + 1e-8f);
        float inv_k = 1.0f / (sqrtf(kss) + 1e-8f);
        float s = dot * inv_q * inv_k * 2.0f;     // / TEMPERATURE(0.5)
        float z = -s;                              // -log_sigmoid(s)
        loss = fmaxf(z, 0.f) + log1pf(expf(-fabsf(z)));
    }
    if (lane == 0 && w < NUM_POS) s_loss[w] = loss;
    __syncthreads();

    if (tid == 0) {
        float sum = 0.f;
#pragma unroll
        for (int i = 0; i < NUM_POS; i++) sum += (i < cnt) ? s_loss[i] : 0.f;
        g_per[b] = (cnt > 0) ? (sum / (float)cnt) : 0.f;
        __threadfence();
        unsigned t = atomicAdd(&g_counter, 1u);
        s_last = (t == (unsigned)(gridDim.x - 1)) ? 1 : 0;
    }
    __syncthreads();

    if (s_last) {
        double acc = 0.0;
        for (int i = tid; i < B; i += 512) acc += (double)g_per[i];
        s_red[tid] = acc;
        __syncthreads();
        for (int s = 256; s; s >>= 1) {
            if (tid < s) s_red[tid] += s_red[tid + s];
            __syncthreads();
        }
        if (tid == 0) out[0] = (float)(s_red[0] / (double)B);
    }
}

extern "C" void kernel_launch(void* const* d_in, const int* in_sizes, int n_in,
                              void* d_out, int out_size) {
    const float* xq   = (const float*)d_in[0];
    const int*   xlab = (const int*)  d_in[1];
    const float* qf   = (const float*)d_in[2];
    const int*   qlab = (const int*)  d_in[3];

    int B  = in_sizes[0] / D_DIM;                 // 4096
    int K  = in_sizes[2] / D_DIM;                 // 131072
    int Kp = (K + STRIDEQ - 1) / STRIDEQ;         // 13108

    int warps  = Kp + B;
    int blocks = (warps * 32 + 255) / 256;
    prep_labels  <<<blocks, 256>>>(xlab, qlab, B, Kp);
    select_kernel<<<B, 256>>>(B, Kp);
    loss_kernel  <<<B, 512>>>(xq, qf, (float*)d_out, B);
}